// round 14
// baseline (speedup 1.0000x reference)
#include <cuda_runtime.h>
#include <cuda_bf16.h>
#include <cuda_fp16.h>
#include <math.h>
#include <stdint.h>

// ---------------- Problem constants ----------------
#define B_  4
#define T_  1024
#define BT  (B_*T_)        // 4096
#define E_  768
#define E3  2304           // fused QKV width
#define H_  12
#define HD  64
#define L_  6
#define FF  3072
#define V_  50257
#define EPS 1e-5f

#define GEMM_SMEM    98560   // MT=128: 2 x 48KB ring (+align); epilogue reuses
#define GEMM64_SMEM  65792   // MT=64:  2 x 32KB ring (+align)
#define GEMM16_SMEM  67840   // head:   2 x 32KB ring; epilogue 67.5KB
#define ATT_SMEM     33024
#define STAGE_LD     132

// weight scratch offsets (elements)
#define WQKV_SZ   589824
#define LAYER_SZ  7077888
#define WO_OFF    1769472
#define W1_OFF    2359296
#define W2_OFF    4718592
#define HEAD_OFF  42467328
#define WTOT      81064704

// ---------------- Device scratch (no allocs allowed) ----------------
__device__ float g_x  [BT * E_];
__device__ __half g_xn_h[BT * E_];
__device__ __half g_xn_l[BT * E_];
__device__ __half g_qkv_h[BT * E3];
__device__ __half g_qkv_l[BT * E3];
__device__ __half g_att_h[BT * E_];
__device__ __half g_att_l[BT * E_];
__device__ __half g_ff_h[BT * FF];
__device__ __half g_ff_l[BT * FF];
__device__ __half g_w_h[WTOT];

// ---------------- helpers ----------------
__device__ __forceinline__ uint32_t smem_u32(const void* p) {
    uint32_t a;
    asm("{ .reg .u64 t; cvta.to.shared.u64 t, %1; cvt.u32.u64 %0, t; }" : "=r"(a) : "l"(p));
    return a;
}
// [R][64] 16-bit tile, 128B rows; conflict-free ldmatrix swizzle
__device__ __forceinline__ uint32_t voff(uint32_t r, uint32_t k) {
    return r * 128u + ((((k >> 3) & 7u) ^ (r & 7u)) << 4) + (k & 7u) * 2u;
}
__device__ __forceinline__ void ldmx4(uint32_t r[4], uint32_t addr) {
    asm volatile("ldmatrix.sync.aligned.m8n8.x4.shared.b16 {%0,%1,%2,%3}, [%4];"
                 : "=r"(r[0]), "=r"(r[1]), "=r"(r[2]), "=r"(r[3]) : "r"(addr));
}
__device__ __forceinline__ void mma16816h(float c[4], const uint32_t a[4], const uint32_t b[2]) {
    asm volatile(
        "mma.sync.aligned.m16n8k16.row.col.f32.f16.f16.f32 "
        "{%0,%1,%2,%3}, {%4,%5,%6,%7}, {%8,%9}, {%0,%1,%2,%3};"
        : "+f"(c[0]), "+f"(c[1]), "+f"(c[2]), "+f"(c[3])
        : "r"(a[0]), "r"(a[1]), "r"(a[2]), "r"(a[3]), "r"(b[0]), "r"(b[1]));
}
__device__ __forceinline__ void cp16(uint32_t dst, const void* src, uint32_t sz) {
    asm volatile("cp.async.cg.shared.global [%0], [%1], 16, %2;"
                 :: "r"(dst), "l"(src), "r"(sz) : "memory");
}
#define CP_COMMIT() asm volatile("cp.async.commit_group;" ::: "memory")
#define CP_WAIT(n)  asm volatile("cp.async.wait_group %0;" :: "n"(n) : "memory")
__device__ __forceinline__ uint32_t pack_h2(__half a, __half b) {
    __half2 t = __halves2half2(a, b);
    return *(uint32_t*)&t;
}

// ---------------- Weight transpose -> fp16 single ----------------
__global__ void wsplit_qkv_all(const float* __restrict__ Wq, const float* __restrict__ Wk,
                               const float* __restrict__ Wv, __half* __restrict__ oh0) {
    __shared__ float t[32][33];
    const int z = blockIdx.z, l = z / 3, w = z - l * 3;
    const float* W = (w == 0 ? Wq : (w == 1 ? Wk : Wv)) + (size_t)l * H_ * E_ * HD;
    __half* oh = oh0 + (size_t)l * LAYER_SZ + (size_t)w * WQKV_SZ;
    const int K = E_;
    const int k0 = blockIdx.x * 32, n0 = blockIdx.y * 32;
    const int tx = threadIdx.x & 31, ty = threadIdx.x >> 5;
    #pragma unroll
    for (int i = 0; i < 32; i += 8) {
        int k = k0 + ty + i, n = n0 + tx;
        t[ty + i][tx] = W[((size_t)(n >> 6) * K + k) * 64 + (n & 63)];
    }
    __syncthreads();
    #pragma unroll
    for (int i = 0; i < 32; i += 8) {
        int n = n0 + ty + i, k = k0 + tx;
        oh[(size_t)n * K + k] = __float2half_rn(t[tx][ty + i]);
    }
}

__global__ void wsplit_all0(const float* __restrict__ W0, long wstride,
                            __half* __restrict__ oh0, long ostride, int K, int N) {
    __shared__ float t[32][33];
    const float* W = W0 + (size_t)blockIdx.z * wstride;
    __half* oh = oh0 + (size_t)blockIdx.z * ostride;
    const int k0 = blockIdx.x * 32, n0 = blockIdx.y * 32;
    const int tx = threadIdx.x & 31, ty = threadIdx.x >> 5;
    #pragma unroll
    for (int i = 0; i < 32; i += 8) {
        int k = k0 + ty + i, n = n0 + tx;
        t[ty + i][tx] = W[(size_t)k * N + n];
    }
    __syncthreads();
    #pragma unroll
    for (int i = 0; i < 32; i += 8) {
        int n = n0 + ty + i, k = k0 + tx;
        oh[(size_t)n * K + k] = __float2half_rn(t[tx][ty + i]);
    }
}

__global__ void wsplit16_kernel(const float* __restrict__ W,
                                __half* __restrict__ oh, int K, int N) {
    __shared__ float t[32][33];
    const int k0 = blockIdx.x * 32, n0 = blockIdx.y * 32;
    const int tx = threadIdx.x & 31, ty = threadIdx.x >> 5;
    #pragma unroll
    for (int i = 0; i < 32; i += 8) {
        int k = k0 + ty + i, n = n0 + tx;
        t[ty + i][tx] = (n < N) ? W[(size_t)k * N + n] : 0.f;
    }
    __syncthreads();
    #pragma unroll
    for (int i = 0; i < 32; i += 8) {
        int n = n0 + ty + i, k = k0 + tx;
        if (n < N)
            oh[(size_t)n * K + k] = __float2half_rn(t[tx][ty + i]);
    }
}

// ---------------- 2-pass fp16 GEMM, K-chunk 64, 2-stage ring ----------------
// A: [M][K] fp16 hi/lo. B: [N][K] fp16 single. M % MT == 0, N % 128 == 0, K % 64 == 0.
// EPI 1: relu(+bias) -> fp16 hi/lo. EPI 2: res+(+bias) -> fp32 C. EPI 3: (+bias) -> fp16 hi/lo.
template<int MT, int EPI>
__global__ void __launch_bounds__(256, 2)
gemm_h2(const __half* __restrict__ Ah, const __half* __restrict__ Al,
        const __half* __restrict__ B,
        const float* __restrict__ bias, const float* __restrict__ res,
        float* C, __half* __restrict__ Ch, __half* __restrict__ Cl,
        int N, int K) {
    extern __shared__ char smraw[];
    uint32_t raw = smem_u32(smraw);
    uint32_t sb  = (raw + 255u) & ~255u;
    char* smp    = smraw + (sb - raw);

    constexpr int ASZ    = MT * 128;        // bytes per A array per stage (64 k)
    constexpr int STG    = 2 * ASZ + 16384; // + B (128 rows x 128B)
    constexpr int MTILES = MT / 32;

    const int tid  = threadIdx.x;
    const int lane = tid & 31;
    const int wid  = tid >> 5;
    const int wm   = wid >> 2;
    const int wn   = wid & 3;
    const int m0   = blockIdx.x * MT;
    const int n0   = blockIdx.y * 128;

    int rA, kA;
    if (MT == 128) { rA = tid >> 1; kA = (tid & 1) * 32; }   // 4 chunks/thread/array
    else           { rA = tid >> 2; kA = (tid & 3) * 16; }   // 2 chunks/thread/array
    const __half* apH = Ah + (size_t)(m0 + rA) * K + kA;
    const __half* apL = Al + (size_t)(m0 + rA) * K + kA;
    const int rB = tid >> 1, kB = (tid & 1) * 32;
    const __half* bp = B + (size_t)(n0 + rB) * K + kB;

    float acc[MTILES][4][4];
    #pragma unroll
    for (int i = 0; i < MTILES; i++)
        #pragma unroll
        for (int j = 0; j < 4; j++)
            #pragma unroll
            for (int q = 0; q < 4; q++) acc[i][j][q] = 0.f;

    const int NC = K >> 6;

    auto ISSUE = [&](int c) {
        uint32_t b0 = sb + (c & 1) * STG;
        const int ko = c << 6;
        if (MT == 128) {
            #pragma unroll
            for (int j = 0; j < 4; j++) {
                uint32_t o = voff(rA, kA + j * 8);
                cp16(b0 + o,       apH + ko + j * 8, 16u);
                cp16(b0 + ASZ + o, apL + ko + j * 8, 16u);
            }
        } else {
            #pragma unroll
            for (int j = 0; j < 2; j++) {
                uint32_t o = voff(rA, kA + j * 8);
                cp16(b0 + o,       apH + ko + j * 8, 16u);
                cp16(b0 + ASZ + o, apL + ko + j * 8, 16u);
            }
        }
        #pragma unroll
        for (int j = 0; j < 4; j++) {
            uint32_t o = voff(rB, kB + j * 8);
            cp16(b0 + 2*ASZ + o, bp + ko + j * 8, 16u);
        }
    };
    auto MMA = [&](int s) {
        uint32_t base = sb + s * STG;
        const uint32_t arow = wm * (MT/2) + (lane & 15);
        const uint32_t koffA = (lane & 16) ? 8u : 0u;
        const uint32_t nrow = wn * 32 + (lane & 7) + ((lane & 16) ? 8 : 0);
        const uint32_t koffB = (lane & 8) ? 8u : 0u;
        #pragma unroll
        for (int ks = 0; ks < 4; ks++) {
            uint32_t ah[MTILES][4], al[MTILES][4], bh[4][2];
            #pragma unroll
            for (int mt = 0; mt < MTILES; mt++) {
                uint32_t off = voff(arow + mt * 16, ks * 16 + koffA);
                ldmx4(ah[mt], base + off);
                ldmx4(al[mt], base + ASZ + off);
            }
            #pragma unroll
            for (int g = 0; g < 2; g++) {
                uint32_t off = voff(nrow + g * 16, ks * 16 + koffB);
                uint32_t t[4];
                ldmx4(t, base + 2*ASZ + off);
                bh[2*g][0] = t[0]; bh[2*g][1] = t[1];
                bh[2*g+1][0] = t[2]; bh[2*g+1][1] = t[3];
            }
            #pragma unroll
            for (int mt = 0; mt < MTILES; mt++)
                #pragma unroll
                for (int nt = 0; nt < 4; nt++) {
                    mma16816h(acc[mt][nt], ah[mt], bh[nt]);
                    mma16816h(acc[mt][nt], al[mt], bh[nt]);
                }
        }
    };

    ISSUE(0); CP_COMMIT();
    if (NC > 1) { ISSUE(1); CP_COMMIT(); }

    for (int c = 0; c < NC; c++) {
        const int rem = NC - 1 - c;
        if (rem >= 1) CP_WAIT(1);
        else          CP_WAIT(0);
        __syncthreads();                  // stage c data visible to all
        MMA(c & 1);
        __syncthreads();                  // all reads of stage c done
        if (c + 2 < NC) { ISSUE(c + 2); CP_COMMIT(); }
    }

    // ---- epilogue: regs -> smem stage (MT x 128, stride 132) -> gmem ----
    float* stage = (float*)smp;
    {
        const int r0 = wm * (MT/2) + (lane >> 2);
        const int c0 = wn * 32 + (lane & 3) * 2;
        #pragma unroll
        for (int mt = 0; mt < MTILES; mt++)
            #pragma unroll
            for (int nt = 0; nt < 4; nt++) {
                int r = r0 + mt * 16, cc = c0 + nt * 8;
                float2 p0; p0.x = acc[mt][nt][0]; p0.y = acc[mt][nt][1];
                float2 p1; p1.x = acc[mt][nt][2]; p1.y = acc[mt][nt][3];
                *(float2*)&stage[r * STAGE_LD + cc]       = p0;
                *(float2*)&stage[(r + 8) * STAGE_LD + cc] = p1;
            }
    }
    __syncthreads();

    constexpr int ITER = MT / 8;
    #pragma unroll 4
    for (int j = 0; j < ITER; j++) {
        int lin = j * 256 + tid;
        int rr = lin >> 5;
        int cg = (lin & 31) * 4;
        int n = n0 + cg;
        float4 v = *(float4*)&stage[rr * STAGE_LD + cg];
        if (bias) {
            float4 bb = *(const float4*)(bias + n);
            v.x += bb.x; v.y += bb.y; v.z += bb.z; v.w += bb.w;
        }
        size_t base = (size_t)(m0 + rr) * N + n;
        if (EPI == 2) {
            float4 rr4 = *(const float4*)(res + base);
            v.x += rr4.x; v.y += rr4.y; v.z += rr4.z; v.w += rr4.w;
            *(float4*)(C + base) = v;
        } else {
            if (EPI == 1) {
                v.x = fmaxf(v.x, 0.f); v.y = fmaxf(v.y, 0.f);
                v.z = fmaxf(v.z, 0.f); v.w = fmaxf(v.w, 0.f);
            }
            __half h0 = __float2half_rn(v.x), h1 = __float2half_rn(v.y);
            __half h2 = __float2half_rn(v.z), h3 = __float2half_rn(v.w);
            uint2 hp; hp.x = pack_h2(h0, h1); hp.y = pack_h2(h2, h3);
            *(uint2*)(Ch + base) = hp;
            uint2 lp;
            lp.x = pack_h2(__float2half_rn(v.x - __half2float(h0)),
                           __float2half_rn(v.y - __half2float(h1)));
            lp.y = pack_h2(__float2half_rn(v.z - __half2float(h2)),
                           __float2half_rn(v.w - __half2float(h3)));
            *(uint2*)(Cl + base) = lp;
        }
    }
}

// ---------------- fp16 single-pass GEMM (head, 128x128, K-chunk 64) ----------------
__global__ void __launch_bounds__(256, 2)
gemm16(const __half* __restrict__ Ah, const __half* __restrict__ Bh,
       const float* __restrict__ bias, float* __restrict__ C,
       int N, int K) {
    extern __shared__ char smraw[];
    uint32_t raw = smem_u32(smraw);
    uint32_t sb  = (raw + 255u) & ~255u;
    char* smp    = smraw + (sb - raw);

    constexpr int STG = 32768;     // A 16KB + B 16KB

    const int tid  = threadIdx.x;
    const int lane = tid & 31;
    const int wid  = tid >> 5;
    const int wm   = wid >> 2;
    const int wn   = wid & 3;
    const int m0   = blockIdx.x * 128;
    const int n0   = blockIdx.y * 128;

    const int r_ = tid >> 1;
    const int kh = (tid & 1) * 32;
    const __half* apH = Ah + (size_t)(m0 + r_) * K + kh;
    const int ng = n0 + r_;
    const bool nvB = (ng < N);
    const int ngc = nvB ? ng : (N - 1);
    const uint32_t bsz = nvB ? 16u : 0u;
    const __half* bpH = Bh + (size_t)ngc * K + kh;

    float acc[4][4][4];
    #pragma unroll
    for (int i = 0; i < 4; i++)
        #pragma unroll
        for (int j = 0; j < 4; j++)
            #pragma unroll
            for (int q = 0; q < 4; q++) acc[i][j][q] = 0.f;

    const int NC = K >> 6;

    auto ISSUE = [&](int c) {
        uint32_t b0 = sb + (c & 1) * STG;
        const int ko = c << 6;
        #pragma unroll
        for (int j = 0; j < 4; j++) {
            uint32_t o = voff(r_, kh + j * 8);
            cp16(b0 + o,         apH + ko + j * 8, 16u);
            cp16(b0 + 16384 + o, bpH + ko + j * 8, bsz);
        }
    };
    auto MMA = [&](int s) {
        uint32_t base = sb + s * STG;
        const uint32_t arow = wm * 64 + (lane & 15);
        const uint32_t koffA = (lane & 16) ? 8u : 0u;
        const uint32_t nrow = wn * 32 + (lane & 7) + ((lane & 16) ? 8 : 0);
        const uint32_t koffB = (lane & 8) ? 8u : 0u;
        #pragma unroll
        for (int ks = 0; ks < 4; ks++) {
            uint32_t ah[4][4], bh[4][2];
            #pragma unroll
            for (int mt = 0; mt < 4; mt++) {
                uint32_t off = voff(arow + mt * 16, ks * 16 + koffA);
                ldmx4(ah[mt], base + off);
            }
            #pragma unroll
            for (int g = 0; g < 2; g++) {
                uint32_t off = voff(nrow + g * 16, ks * 16 + koffB);
                uint32_t t[4];
                ldmx4(t, base + 16384 + off);
                bh[2*g][0] = t[0]; bh[2*g][1] = t[1];
                bh[2*g+1][0] = t[2]; bh[2*g+1][1] = t[3];
            }
            #pragma unroll
            for (int mt = 0; mt < 4; mt++)
                #pragma unroll
                for (int nt = 0; nt < 4; nt++)
                    mma16816h(acc[mt][nt], ah[mt], bh[nt]);
        }
    };

    ISSUE(0); CP_COMMIT();
    if (NC > 1) { ISSUE(1); CP_COMMIT(); }

    for (int c = 0; c < NC; c++) {
        const int rem = NC - 1 - c;
        if (rem >= 1) CP_WAIT(1);
        else          CP_WAIT(0);
        __syncthreads();
        MMA(c & 1);
        __syncthreads();
        if (c + 2 < NC) { ISSUE(c + 2); CP_COMMIT(); }
    }

    float* stage = (float*)smp;
    {
        const int r0 = wm * 64 + (lane >> 2);
        const int c0 = wn * 32 + (lane & 3) * 2;
        #pragma unroll
        for (int mt = 0; mt < 4; mt++)
            #pragma unroll
            for (int nt = 0; nt < 4; nt++) {
                int r = r0 + mt * 16, cc = c0 + nt * 8;
                float2 p0; p0.x = acc[mt][nt][0]; p0.y = acc[mt][nt][1];
                float2 p1; p1.x = acc[mt][nt][2]; p1.y = acc[mt][nt][3];
                *(float2*)&stage[r * STAGE_LD + cc]       = p0;
                *(float2*)&stage[(r + 8) * STAGE_LD + cc] = p1;
            }
    }
    __syncthreads();

    #pragma unroll 4
    for (int j = 0; j < 16; j++) {
        int lin = j * 256 + tid;
        int rr = lin >> 5;
        int cg = (lin & 31) * 4;
        #pragma unroll
        for (int q = 0; q < 4; q++) {
            int n = n0 + cg + q;
            if (n < N) {
                float v = stage[rr * STAGE_LD + cg + q];
                if (bias) v += bias[n];
                C[(size_t)(m0 + rr) * N + n] = v;
            }
        }
    }
}

// ---------------- LayerNorm core (192 threads, float4) ----------------
__device__ __forceinline__ void ln_body(float4 v, const float* __restrict__ g,
                                        const float* __restrict__ b,
                                        __half* __restrict__ yh, __half* __restrict__ yl,
                                        size_t rb, int tid) {
    float s  = v.x + v.y + v.z + v.w;
    float ss = v.x*v.x + v.y*v.y + v.z*v.z + v.w*v.w;
    #pragma unroll
    for (int off = 16; off > 0; off >>= 1) {
        s  += __shfl_down_sync(0xffffffffu, s,  off);
        ss += __shfl_down_sync(0xffffffffu, ss, off);
    }
    __shared__ float sh_s[6], sh_ss[6];
    int wid = tid >> 5, lane = tid & 31;
    if (lane == 0) { sh_s[wid] = s; sh_ss[wid] = ss; }
    __syncthreads();
    float tot = 0.f, tots = 0.f;
    #pragma unroll
    for (int i = 0; i < 6; i++) { tot += sh_s[i]; tots += sh_ss[i]; }
    float mean = tot * (1.0f / E_);
    float var  = tots * (1.0f / E_) - mean * mean;
    float rstd = rsqrtf(var + EPS);
    float4 gg = *(const float4*)(g + tid * 4);
    float4 bb = *(const float4*)(b + tid * 4);
    float y0 = (v.x - mean) * rstd * gg.x + bb.x;
    float y1 = (v.y - mean) * rstd * gg.y + bb.y;
    float y2 = (v.z - mean) * rstd * gg.z + bb.z;
    float y3 = (v.w - mean) * rstd * gg.w + bb.w;
    __half h0 = __float2half_rn(y0), h1 = __float2half_rn(y1);
    __half h2 = __float2half_rn(y2), h3 = __float2half_rn(y3);
    uint2 hp; hp.x = pack_h2(h0, h1); hp.y = pack_h2(h2, h3);
    *(uint2*)(yh + rb + tid * 4) = hp;
    uint2 lp;
    lp.x = pack_h2(__float2half_rn(y0 - __half2float(h0)),
                   __float2half_rn(y1 - __half2float(h1)));
    lp.y = pack_h2(__float2half_rn(y2 - __half2float(h2)),
                   __float2half_rn(y3 - __half2float(h3)));
    *(uint2*)(yl + rb + tid * 4) = lp;
}

__global__ void ln_kernel(const float* __restrict__ x,
                          const float* __restrict__ g,
                          const float* __restrict__ b,
                          __half* __restrict__ yh, __half* __restrict__ yl) {
    const int row = blockIdx.x, tid = threadIdx.x;
    size_t rb = (size_t)row * E_;
    float4 v = *(const float4*)(x + rb + tid * 4);
    ln_body(v, g, b, yh, yl, rb, tid);
}

__global__ void embed_ln_kernel(const int* __restrict__ idx,
                                const float* __restrict__ tok,
                                const float* __restrict__ pos,
                                const float* __restrict__ g,
                                const float* __restrict__ b,
                                float* __restrict__ x,
                                __half* __restrict__ yh, __half* __restrict__ yl) {
    const int row = blockIdx.x, tid = threadIdx.x;
    const int t = row & (T_ - 1);
    const int token = idx[row];
    float4 tv = *(const float4*)(tok + (size_t)token * E_ + tid * 4);
    float4 pv = *(const float4*)(pos + (size_t)t * E_ + tid * 4);
    float4 v; v.x = tv.x + pv.x; v.y = tv.y + pv.y; v.z = tv.z + pv.z; v.w = tv.w + pv.w;
    size_t rb = (size_t)row * E_;
    *(float4*)(x + rb + tid * 4) = v;
    ln_body(v, g, b, yh, yl, rb, tid);
}

// ---------------- Tensor-core flash attention (fused-QKV input, stride E3) ----------------
__global__ void __launch_bounds__(128, 3)
attn_mma(const __half* __restrict__ QKVh, const __half* __restrict__ QKVl,
         __half* __restrict__ Oh, __half* __restrict__ Ol) {
    extern __shared__ char smraw[];
    uint32_t raw = smem_u32(smraw);
    uint32_t sb  = (raw + 255u) & ~255u;
    char* smp    = smraw + (sb - raw);
    const uint32_t s_kh = sb, s_kl = sb + 8192, s_vh = sb + 16384, s_vl = sb + 24576;
    char *p_kh = smp, *p_kl = smp + 8192, *p_vh = smp + 16384, *p_vl = smp + 24576;

    const int qb = blockIdx.x, bhid = blockIdx.y;
    const int b = bhid / H_, h = bhid % H_;
    const int tid = threadIdx.x, lane = tid & 31, wq = tid >> 5;
    const float scale = rsqrtf((float)E_);

    const uint32_t koffA = (lane & 16) ? 8u : 0u;
    const uint32_t brow  = (lane & 7) + ((lane & 16) ? 8 : 0);
    const uint32_t koffB = (lane & 8) ? 8u : 0u;

    uint32_t aQh[4][4], aQl[4][4];
    {
        int r = tid >> 1, hf = (tid & 1) * 32;
        size_t qoff = (size_t)(b*T_ + qb*64 + r) * E3 + h*64 + hf;
        const uint4* qph = (const uint4*)(QKVh + qoff);
        const uint4* qpl = (const uint4*)(QKVl + qoff);
        #pragma unroll
        for (int j = 0; j < 4; j++) {
            *(uint4*)(p_kh + voff(r, hf + j*8)) = qph[j];
            *(uint4*)(p_kl + voff(r, hf + j*8)) = qpl[j];
        }
        __syncthreads();
        #pragma unroll
        for (int ks = 0; ks < 4; ks++) {
            ldmx4(aQh[ks], s_kh + voff(wq*16 + (lane & 15), ks*16 + koffA));
            ldmx4(aQl[ks], s_kl + voff(wq*16 + (lane & 15), ks*16 + koffA));
        }
        __syncthreads();
    }

    float m0 = -1e30f, m1 = -1e30f, l0 = 0.f, l1 = 0.f;
    float O[8][4];
    #pragma unroll
    for (int nt = 0; nt < 8; nt++)
        #pragma unroll
        for (int q = 0; q < 4; q++) O[nt][q] = 0.f;

    const int q0 = qb*64 + wq*16 + (lane >> 2);
    const int q1 = q0 + 8;

    for (int st0 = 0; st0 <= qb*64; st0 += 64) {
        {
            int s = tid >> 1, hf = (tid & 1) * 32;
            size_t koffg = (size_t)(b*T_ + st0 + s) * E3 + 768 + h*64 + hf;
            size_t voffg = (size_t)(b*T_ + st0 + s) * E3 + 1536 + h*64 + hf;
            const uint4* kph = (const uint4*)(QKVh + koffg);
            const uint4* kpl = (const uint4*)(QKVl + koffg);
            #pragma unroll
            for (int j = 0; j < 4; j++) {
                *(uint4*)(p_kh + voff(s, hf + j*8)) = kph[j];
                *(uint4*)(p_kl + voff(s, hf + j*8)) = kpl[j];
            }
            uint4 tvh[4], tvl[4];
            const uint4* vph = (const uint4*)(QKVh + voffg);
            const uint4* vpl = (const uint4*)(QKVl + voffg);
            #pragma unroll
            for (int j = 0; j < 4; j++) { tvh[j] = vph[j]; tvl[j] = vpl[j]; }
            const __half* hv = (const __half*)tvh;
            const __half* lv = (const __half*)tvl;
            #pragma unroll
            for (int j = 0; j < 32; j++) {
                *(__half*)(p_vh + voff(hf + j, s)) = hv[j];
                *(__half*)(p_vl + voff(hf + j, s)) = lv[j];
            }
        }
        __syncthreads();

        float S[8][4];
        #pragma unroll
        for (int nt = 0; nt < 8; nt++)
            #pragma unroll
            for (int q = 0; q < 4; q++) S[nt][q] = 0.f;
        #pragma unroll
        for (int ks = 0; ks < 4; ks++) {
            uint32_t bKh[8][2], bKl[8][2];
            #pragma unroll
            for (int g = 0; g < 4; g++) {
                uint32_t t[4];
                ldmx4(t, s_kh + voff(g*16 + brow, ks*16 + koffB));
                bKh[2*g][0] = t[0]; bKh[2*g][1] = t[1];
                bKh[2*g+1][0] = t[2]; bKh[2*g+1][1] = t[3];
                ldmx4(t, s_kl + voff(g*16 + brow, ks*16 + koffB));
                bKl[2*g][0] = t[0]; bKl[2*g][1] = t[1];
                bKl[2*g+1][0] = t[2]; bKl[2*g+1][1] = t[3];
            }
            #pragma unroll
            for (int nt = 0; nt < 8; nt++) {
                mma16816h(S[nt], aQh[ks], bKh[nt]);
                mma16816h(S[nt], aQl[ks], bKh[nt]);
                mma16816h(S[nt], aQh[ks], bKl[nt]);
            }
        }

        const bool diag = (st0 == qb*64);
        #pragma unroll
        for (int nt = 0; nt < 8; nt++) {
            S[nt][0] *= scale; S[nt][1] *= scale; S[nt][2] *= scale; S[nt][3] *= scale;
            if (diag) {
                int sg = st0 + nt*8 + (lane & 3)*2;
                if (sg     > q0) S[nt][0] = -1e30f;
                if (sg + 1 > q0) S[nt][1] = -1e30f;
                if (sg     > q1) S[nt][2] = -1e30f;
                if (sg + 1 > q1) S[nt][3] = -1e30f;
            }
        }

        float rx0 = -1e30f, rx1 = -1e30f;
        #pragma unroll
        for (int nt = 0; nt < 8; nt++) {
            rx0 = fmaxf(rx0, fmaxf(S[nt][0], S[nt][1]));
            rx1 = fmaxf(rx1, fmaxf(S[nt][2], S[nt][3]));
        }
        rx0 = fmaxf(rx0, __shfl_xor_sync(0xffffffffu, rx0, 1));
        rx0 = fmaxf(rx0, __shfl_xor_sync(0xffffffffu, rx0, 2));
        rx1 = fmaxf(rx1, __shfl_xor_sync(0xffffffffu, rx1, 1));
        rx1 = fmaxf(rx1, __shfl_xor_sync(0xffffffffu, rx1, 2));
        float mn0 = fmaxf(m0, rx0), mn1 = fmaxf(m1, rx1);
        float c0 = __expf(m0 - mn0), c1 = __expf(m1 - mn1);

        float rs0 = 0.f, rs1 = 0.f;
        uint32_t aPh[4][4], aPl[4][4];
        #pragma unroll
        for (int ks = 0; ks < 4; ks++) {
            #pragma unroll
            for (int hf = 0; hf < 2; hf++) {
                int nt = 2*ks + hf;
                float p0 = __expf(S[nt][0] - mn0);
                float p1 = __expf(S[nt][1] - mn0);
                float p2 = __expf(S[nt][2] - mn1);
                float p3 = __expf(S[nt][3] - mn1);
                rs0 += p0 + p1; rs1 += p2 + p3;
                __half h0 = __float2half_rn(p0), h1 = __float2half_rn(p1);
                __half h2 = __float2half_rn(p2), h3 = __float2half_rn(p3);
                aPh[ks][2*hf]     = pack_h2(h0, h1);
                aPh[ks][2*hf + 1] = pack_h2(h2, h3);
                aPl[ks][2*hf]     = pack_h2(__float2half_rn(p0 - __half2float(h0)),
                                            __float2half_rn(p1 - __half2float(h1)));
                aPl[ks][2*hf + 1] = pack_h2(__float2half_rn(p2 - __half2float(h2)),
                                            __float2half_rn(p3 - __half2float(h3)));
            }
        }
        rs0 += __shfl_xor_sync(0xffffffffu, rs0, 1);
        rs0 += __shfl_xor_sync(0xffffffffu, rs0, 2);
        rs1 += __shfl_xor_sync(0xffffffffu, rs1, 1);
        rs1 += __shfl_xor_sync(0xffffffffu, rs1, 2);
        l0 = l0 * c0 + rs0;
        l1 = l1 * c1 + rs1;

        #pragma unroll
        for (int nt = 0; nt < 8; nt++) {
            O[nt][0] *= c0; O[nt][1] *= c0; O[nt][2] *= c1; O[nt][3] *= c1;
        }

        #pragma unroll
        for (int ks = 0; ks < 4; ks++) {
            uint32_t bVh[8][2], bVl[8][2];
            #pragma unroll
            for (int g = 0; g < 4; g++) {
                uint32_t t[4];
                ldmx4(t, s_vh + voff(g*16 + brow, ks*16 + koffB));
                bVh[2*g][0] = t[0]; bVh[2*g][1] = t[1];
                bVh[2*g+1][0] = t[2]; bVh[2*g+1][1] = t[3];
                ldmx4(t, s_vl + voff(g*16 + brow, ks*16 + koffB));
                bVl[2*g][0] = t[0]; bVl[2*g][1] = t[1];
                bVl[2*g+1][0] = t[2]; bVl[2*g+1][1] = t[3];
            }
            #pragma unroll
            for (int nt = 0; nt < 8; nt++) {
                mma16816h(O[nt], aPh[ks], bVh[nt]);
                mma16816h(O[nt], aPl[ks], bVh[nt]);
                mma16816h(O[nt], aPh[ks], bVl[nt]);
            }
        }
        m0 = mn0; m1 = mn1;
        __syncthreads();
    }

    float i0 = 1.f / l0, i1 = 1.f / l1;
    size_t base0 = (size_t)(b*T_ + q0) * E_ + h*64 + (lane & 3)*2;
    size_t base1 = (size_t)(b*T_ + q1) * E_ + h*64 + (lane & 3)*2;
    #pragma unroll
    for (int nt = 0; nt < 8; nt++) {
        int d = nt * 8;
        float v0 = O[nt][0] * i0, v1 = O[nt][1] * i0;
        float v2 = O[nt][2] * i1, v3 = O[nt][3] * i1;
        __half h0 = __float2half_rn(v0), h1 = __float2half_rn(v1);
        __half h2 = __float2half_rn(v2), h3 = __float2half_rn(v3);
        *(uint32_t*)(Oh + base0 + d) = pack_h2(h0, h1);
        *(uint32_t*)(Oh + base1 + d) = pack_h2(h2, h3);
        *(uint32_t*)(Ol + base0 + d) = pack_h2(__float2half_rn(v0 - __half2float(h0)),
                                               __float2half_rn(v1 - __half2float(h1)));
        *(uint32_t*)(Ol + base1 + d) = pack_h2(__float2half_rn(v2 - __half2float(h2)),
                                               __float2half_rn(v3 - __half2float(h3)));
    }
}

// ---------------- Host launch ----------------
extern "C" void kernel_launch(void* const* d_in, const int* in_sizes, int n_in,
                              void* d_out, int out_size) {
    const int*   idx     = (const int*)  d_in[0];
    const float* tok_emb = (const float*)d_in[1];
    const float* pos_emb = (const float*)d_in[2];
    const float* Wq      = (const float*)d_in[3];
    const float* Wk      = (const float*)d_in[4];
    const float* Wv      = (const float*)d_in[5];
    const float* Wo      = (const float*)d_in[6];
    const float* bo      = (const float*)d_in[7];
    const float* ln1_g   = (const float*)d_in[8];
    const float* ln1_b   = (const float*)d_in[9];
    const float* ln2_g   = (const float*)d_in[10];
    const float* ln2_b   = (const float*)d_in[11];
    const float* W1      = (const float*)d_in[12];
    const float* b1      = (const float*)d_in[13];
    const float* W2      = (const float*)d_in[14];
    const float* b2      = (const float*)d_in[15];
    const float* lnf_g   = (const float*)d_in[16];
    const float* lnf_b   = (const float*)d_in[17];
    const float* Wh      = (const float*)d_in[18];
    const float* bh      = (const float*)d_in[19];
    float* out = (float*)d_out;

    float *x;
    __half *xnh, *xnl, *qkvh, *qkvl, *atth, *attl, *ffh, *ffl, *wh;
    cudaGetSymbolAddress((void**)&x,    g_x);
    cudaGetSymbolAddress((void**)&xnh,  g_xn_h);
    cudaGetSymbolAddress((void**)&xnl,  g_xn_l);
    cudaGetSymbolAddress((void**)&qkvh, g_qkv_h);
    cudaGetSymbolAddress((void**)&qkvl, g_qkv_l);
    cudaGetSymbolAddress((void**)&atth, g_att_h);
    cudaGetSymbolAddress((void**)&attl, g_att_l);
    cudaGetSymbolAddress((void**)&ffh,  g_ff_h);
    cudaGetSymbolAddress((void**)&ffl,  g_ff_l);
    cudaGetSymbolAddress((void**)&wh,   g_w_h);

    cudaFuncSetAttribute((void*)gemm_h2<128,3>, cudaFuncAttributeMaxDynamicSharedMemorySize, GEMM_SMEM);
    cudaFuncSetAttribute((void*)gemm_h2<128,1>, cudaFuncAttributeMaxDynamicSharedMemorySize, GEMM_SMEM);
    cudaFuncSetAttribute((void*)gemm_h2<64,2>,  cudaFuncAttributeMaxDynamicSharedMemorySize, GEMM64_SMEM);
    cudaFuncSetAttribute((void*)gemm16,         cudaFuncAttributeMaxDynamicSharedMemorySize, GEMM16_SMEM);
    cudaFuncSetAttribute((void*)attn_mma,       cudaFuncAttributeMaxDynamicSharedMemorySize, ATT_SMEM);

    dim3 gQKVsplit(24, 24, 18);
    dim3 gWoAll(24, 24, 6);
    dim3 gW1All(24, 96, 6);
    dim3 gW2All(96, 24, 6);
    dim3 gHd(24, (V_+31)/32);
    dim3 gQKV(32, 18);       // 128x128, N=2304
    dim3 gWo(64, 6);         // 64x128, N=768
    dim3 gFF(32, 24);        // 128x128, N=3072
    dim3 gW2(64, 6);         // 64x128, K=3072
    dim3 gV(32, 393);
    dim3 gAttn(T_ / 64, B_ * H_);

    // QKV GEMM of layer 0 at launch index 3 (ncu window)
    embed_ln_kernel<<<BT, 192>>>(idx, tok_emb, pos_emb, ln1_g, ln1_b, x, xnh, xnl);     // 0
    wsplit_qkv_all<<<gQKVsplit, 256>>>(Wq, Wk, Wv, wh);                                 // 1
    wsplit_all0<<<gWoAll, 256>>>(Wo, (long)E_*E_, wh + WO_OFF, (long)LAYER_SZ, E_, E_); // 2

    for (int l = 0; l < L_; l++) {
        size_t lo = (size_t)l * LAYER_SZ;

        if (l > 0)
            ln_kernel<<<BT, 192>>>(x, ln1_g + (size_t)l * E_, ln1_b + (size_t)l * E_, xnh, xnl);

        gemm_h2<128,3><<<gQKV, 256, GEMM_SMEM>>>(xnh, xnl, wh + lo,                     // 3 for l=0
                                                 nullptr, nullptr, nullptr,
                                                 qkvh, qkvl, E3, E_);

        attn_mma<<<gAttn, 128, ATT_SMEM>>>(qkvh, qkvl, atth, attl);

        gemm_h2<64,2><<<gWo, 256, GEMM64_SMEM>>>(atth, attl, wh + lo + WO_OFF,
                                                 bo + (size_t)l * E_, x, x,
                                                 nullptr, nullptr, E_, E_);

        ln_kernel<<<BT, 192>>>(x, ln2_g + (size_t)l * E_, ln2_b + (size_t)l * E_, xnh, xnl);

        if (l == 0)
            wsplit_all0<<<gW1All, 256>>>(W1, (long)E_*FF, wh + W1_OFF, (long)LAYER_SZ, E_, FF);
        gemm_h2<128,1><<<gFF, 256, GEMM_SMEM>>>(xnh, xnl, wh + lo + W1_OFF,
                                                b1 + (size_t)l * FF, nullptr, nullptr,
                                                ffh, ffl, FF, E_);

        if (l == 0)
            wsplit_all0<<<gW2All, 256>>>(W2, (long)FF*E_, wh + W2_OFF, (long)LAYER_SZ, FF, E_);
        gemm_h2<64,2><<<gW2, 256, GEMM64_SMEM>>>(ffh, ffl, wh + lo + W2_OFF,
                                                 b2 + (size_t)l * E_, x, x,
                                                 nullptr, nullptr, E_, FF);
    }

    // fp16 single-pass head
    ln_kernel<<<BT, 192>>>(x, lnf_g, lnf_b, xnh, xnl);
    wsplit16_kernel<<<gHd, 256>>>(Wh, wh + HEAD_OFF, E_, V_);
    gemm16<<<gV, 256, GEMM16_SMEM>>>(xnh, wh + HEAD_OFF, bh, out, V_, E_);

    (void)in_sizes; (void)n_in; (void)out_size;
}

// round 15
// speedup vs baseline: 1.0832x; 1.0832x over previous
#include <cuda_runtime.h>
#include <cuda_bf16.h>
#include <cuda_fp16.h>
#include <math.h>
#include <stdint.h>

// ---------------- Problem constants ----------------
#define B_  4
#define T_  1024
#define BT  (B_*T_)        // 4096
#define E_  768
#define E3  2304           // fused QKV width
#define H_  12
#define HD  64
#define L_  6
#define FF  3072
#define V_  50257
#define EPS 1e-5f

#define GEMM_SMEM    49408   // MT=64: 3 x 16KB ring (+align); epilogue 33.8KB reuses
#define GEMM16_SMEM  68096   // head 128x128: 3 x 16KB ring; epilogue 67.6KB
#define ATT_SMEM     33024
#define STAGE_LD     132

// weight scratch offsets (elements)
#define WQKV_SZ   589824
#define LAYER_SZ  7077888
#define WO_OFF    1769472
#define W1_OFF    2359296
#define W2_OFF    4718592
#define HEAD_OFF  42467328
#define WTOT      81064704

// ---------------- Device scratch (no allocs allowed) ----------------
__device__ float g_x  [BT * E_];
__device__ __half g_xn_h[BT * E_];
__device__ __half g_xn_l[BT * E_];
__device__ __half g_qkv_h[BT * E3];
__device__ __half g_qkv_l[BT * E3];
__device__ __half g_att_h[BT * E_];
__device__ __half g_att_l[BT * E_];
__device__ __half g_ff_h[BT * FF];
__device__ __half g_ff_l[BT * FF];
__device__ __half g_w_h[WTOT];

// ---------------- helpers ----------------
__device__ __forceinline__ uint32_t smem_u32(const void* p) {
    uint32_t a;
    asm("{ .reg .u64 t; cvta.to.shared.u64 t, %1; cvt.u32.u64 %0, t; }" : "=r"(a) : "l"(p));
    return a;
}
// [R][32] 16-bit tile, 64B rows; conflict-free ldmatrix swizzle
__device__ __forceinline__ uint32_t aoff(uint32_t r, uint32_t k) {
    return r * 64u + (((((k) >> 3) & 3u) ^ ((r >> 1) & 3u)) << 4) + (k & 7u) * 2u;
}
// [R][64] 16-bit tile, 128B rows; conflict-free ldmatrix swizzle
__device__ __forceinline__ uint32_t voff(uint32_t r, uint32_t k) {
    return r * 128u + ((((k >> 3) & 7u) ^ (r & 7u)) << 4) + (k & 7u) * 2u;
}
__device__ __forceinline__ void ldmx4(uint32_t r[4], uint32_t addr) {
    asm volatile("ldmatrix.sync.aligned.m8n8.x4.shared.b16 {%0,%1,%2,%3}, [%4];"
                 : "=r"(r[0]), "=r"(r[1]), "=r"(r[2]), "=r"(r[3]) : "r"(addr));
}
__device__ __forceinline__ void mma16816h(float c[4], const uint32_t a[4], const uint32_t b[2]) {
    asm volatile(
        "mma.sync.aligned.m16n8k16.row.col.f32.f16.f16.f32 "
        "{%0,%1,%2,%3}, {%4,%5,%6,%7}, {%8,%9}, {%0,%1,%2,%3};"
        : "+f"(c[0]), "+f"(c[1]), "+f"(c[2]), "+f"(c[3])
        : "r"(a[0]), "r"(a[1]), "r"(a[2]), "r"(a[3]), "r"(b[0]), "r"(b[1]));
}
__device__ __forceinline__ void cp16(uint32_t dst, const void* src, uint32_t sz) {
    asm volatile("cp.async.cg.shared.global [%0], [%1], 16, %2;"
                 :: "r"(dst), "l"(src), "r"(sz) : "memory");
}
#define CP_COMMIT() asm volatile("cp.async.commit_group;" ::: "memory")
#define CP_WAIT(n)  asm volatile("cp.async.wait_group %0;" :: "n"(n) : "memory")
__device__ __forceinline__ uint32_t pack_h2(__half a, __half b) {
    __half2 t = __halves2half2(a, b);
    return *(uint32_t*)&t;
}

// ---------------- Weight transpose -> fp16 single ----------------
__global__ void wsplit_qkv_all(const float* __restrict__ Wq, const float* __restrict__ Wk,
                               const float* __restrict__ Wv, __half* __restrict__ oh0) {
    __shared__ float t[32][33];
    const int z = blockIdx.z, l = z / 3, w = z - l * 3;
    const float* W = (w == 0 ? Wq : (w == 1 ? Wk : Wv)) + (size_t)l * H_ * E_ * HD;
    __half* oh = oh0 + (size_t)l * LAYER_SZ + (size_t)w * WQKV_SZ;
    const int K = E_;
    const int k0 = blockIdx.x * 32, n0 = blockIdx.y * 32;
    const int tx = threadIdx.x & 31, ty = threadIdx.x >> 5;
    #pragma unroll
    for (int i = 0; i < 32; i += 8) {
        int k = k0 + ty + i, n = n0 + tx;
        t[ty + i][tx] = W[((size_t)(n >> 6) * K + k) * 64 + (n & 63)];
    }
    __syncthreads();
    #pragma unroll
    for (int i = 0; i < 32; i += 8) {
        int n = n0 + ty + i, k = k0 + tx;
        oh[(size_t)n * K + k] = __float2half_rn(t[tx][ty + i]);
    }
}

__global__ void wsplit_all0(const float* __restrict__ W0, long wstride,
                            __half* __restrict__ oh0, long ostride, int K, int N) {
    __shared__ float t[32][33];
    const float* W = W0 + (size_t)blockIdx.z * wstride;
    __half* oh = oh0 + (size_t)blockIdx.z * ostride;
    const int k0 = blockIdx.x * 32, n0 = blockIdx.y * 32;
    const int tx = threadIdx.x & 31, ty = threadIdx.x >> 5;
    #pragma unroll
    for (int i = 0; i < 32; i += 8) {
        int k = k0 + ty + i, n = n0 + tx;
        t[ty + i][tx] = W[(size_t)k * N + n];
    }
    __syncthreads();
    #pragma unroll
    for (int i = 0; i < 32; i += 8) {
        int n = n0 + ty + i, k = k0 + tx;
        oh[(size_t)n * K + k] = __float2half_rn(t[tx][ty + i]);
    }
}

__global__ void wsplit16_kernel(const float* __restrict__ W,
                                __half* __restrict__ oh, int K, int N) {
    __shared__ float t[32][33];
    const int k0 = blockIdx.x * 32, n0 = blockIdx.y * 32;
    const int tx = threadIdx.x & 31, ty = threadIdx.x >> 5;
    #pragma unroll
    for (int i = 0; i < 32; i += 8) {
        int k = k0 + ty + i, n = n0 + tx;
        t[ty + i][tx] = (n < N) ? W[(size_t)k * N + n] : 0.f;
    }
    __syncthreads();
    #pragma unroll
    for (int i = 0; i < 32; i += 8) {
        int n = n0 + ty + i, k = k0 + tx;
        if (n < N)
            oh[(size_t)n * K + k] = __float2half_rn(t[tx][ty + i]);
    }
}

// ---------------- 2-pass fp16 GEMM, MT=64 NT=128, K32, 3-stage, 3 CTAs/SM ----------------
// A: [M][K] fp16 hi/lo. B: [N][K] fp16 single. M % 64 == 0, N % 128 == 0, K % 32 == 0.
// EPI 1: relu(+bias) -> fp16 hi/lo. EPI 2: res+(+bias) -> fp32 C. EPI 3: (+bias) -> fp16 hi/lo.
template<int EPI>
__global__ void __launch_bounds__(256, 3)
gemm_h2(const __half* __restrict__ Ah, const __half* __restrict__ Al,
        const __half* __restrict__ B,
        const float* __restrict__ bias, const float* __restrict__ res,
        float* C, __half* __restrict__ Ch, __half* __restrict__ Cl,
        int N, int K) {
    extern __shared__ char smraw[];
    uint32_t raw = smem_u32(smraw);
    uint32_t sb  = (raw + 255u) & ~255u;
    char* smp    = smraw + (sb - raw);

    constexpr int ASZ = 4096;               // 64 rows x 32 k x 2B per A array
    constexpr int STG = 2 * ASZ + 8192;     // + B (128 rows x 64B)

    const int tid  = threadIdx.x;
    const int lane = tid & 31;
    const int wid  = tid >> 5;
    const int wm   = wid >> 2;              // 0..1  (32 M-rows each)
    const int wn   = wid & 3;               // 0..3  (32 N-cols each)
    const int m0   = blockIdx.x * 64;
    const int n0   = blockIdx.y * 128;

    const int rA = tid >> 2;                // 0..63
    const int kA = (tid & 3) * 8;
    const __half* apH = Ah + (size_t)(m0 + rA) * K + kA;
    const __half* apL = Al + (size_t)(m0 + rA) * K + kA;
    const int rB = tid >> 1;                // 0..127
    const int kB = (tid & 1) * 16;
    const __half* bp = B + (size_t)(n0 + rB) * K + kB;

    float acc[2][4][4];
    #pragma unroll
    for (int i = 0; i < 2; i++)
        #pragma unroll
        for (int j = 0; j < 4; j++)
            #pragma unroll
            for (int q = 0; q < 4; q++) acc[i][j][q] = 0.f;

    const int NC = K >> 5;
    const uint32_t oA  = aoff(rA, kA);
    const uint32_t oB0 = aoff(rB, kB), oB1 = aoff(rB, kB + 8);

    auto ISSUE = [&](int c) {
        uint32_t b0 = sb + (c % 3) * STG;
        const int ko = c << 5;
        cp16(b0 + oA,       apH + ko, 16u);
        cp16(b0 + ASZ + oA, apL + ko, 16u);
        cp16(b0 + 2*ASZ + oB0, bp + ko,     16u);
        cp16(b0 + 2*ASZ + oB1, bp + ko + 8, 16u);
    };
    auto MMA = [&](int s) {
        uint32_t base = sb + s * STG;
        const uint32_t arow = wm * 32 + (lane & 15);
        const uint32_t koffA = (lane & 16) ? 8u : 0u;
        const uint32_t nrow = wn * 32 + (lane & 7) + ((lane & 16) ? 8 : 0);
        const uint32_t koffB = (lane & 8) ? 8u : 0u;
        #pragma unroll
        for (int ks = 0; ks < 2; ks++) {
            uint32_t ah[2][4], al[2][4], bh[4][2];
            #pragma unroll
            for (int mt = 0; mt < 2; mt++) {
                uint32_t off = aoff(arow + mt * 16, ks * 16 + koffA);
                ldmx4(ah[mt], base + off);
                ldmx4(al[mt], base + ASZ + off);
            }
            #pragma unroll
            for (int g = 0; g < 2; g++) {
                uint32_t off = aoff(nrow + g * 16, ks * 16 + koffB);
                uint32_t t[4];
                ldmx4(t, base + 2*ASZ + off);
                bh[2*g][0] = t[0]; bh[2*g][1] = t[1];
                bh[2*g+1][0] = t[2]; bh[2*g+1][1] = t[3];
            }
            #pragma unroll
            for (int mt = 0; mt < 2; mt++)
                #pragma unroll
                for (int nt = 0; nt < 4; nt++) {
                    mma16816h(acc[mt][nt], ah[mt], bh[nt]);
                    mma16816h(acc[mt][nt], al[mt], bh[nt]);
                }
        }
    };

    ISSUE(0); CP_COMMIT();
    if (NC > 1) { ISSUE(1); CP_COMMIT(); }

    for (int c = 0; c < NC; c++) {
        const int rem = NC - 1 - c;
        if (rem >= 1) CP_WAIT(1);
        else          CP_WAIT(0);
        __syncthreads();
        if (c + 2 < NC) { ISSUE(c + 2); CP_COMMIT(); }
        MMA(c % 3);
    }
    __syncthreads();

    // ---- epilogue: regs -> smem stage (64 x 128, stride 132) -> gmem ----
    float* stage = (float*)smp;
    {
        const int r0 = wm * 32 + (lane >> 2);
        const int c0 = wn * 32 + (lane & 3) * 2;
        #pragma unroll
        for (int mt = 0; mt < 2; mt++)
            #pragma unroll
            for (int nt = 0; nt < 4; nt++) {
                int r = r0 + mt * 16, cc = c0 + nt * 8;
                float2 p0; p0.x = acc[mt][nt][0]; p0.y = acc[mt][nt][1];
                float2 p1; p1.x = acc[mt][nt][2]; p1.y = acc[mt][nt][3];
                *(float2*)&stage[r * STAGE_LD + cc]       = p0;
                *(float2*)&stage[(r + 8) * STAGE_LD + cc] = p1;
            }
    }
    __syncthreads();

    #pragma unroll 4
    for (int j = 0; j < 8; j++) {
        int lin = j * 256 + tid;
        int rr = lin >> 5;
        int cg = (lin & 31) * 4;
        int n = n0 + cg;
        float4 v = *(float4*)&stage[rr * STAGE_LD + cg];
        if (bias) {
            float4 bb = *(const float4*)(bias + n);
            v.x += bb.x; v.y += bb.y; v.z += bb.z; v.w += bb.w;
        }
        size_t base = (size_t)(m0 + rr) * N + n;
        if (EPI == 2) {
            float4 rr4 = *(const float4*)(res + base);
            v.x += rr4.x; v.y += rr4.y; v.z += rr4.z; v.w += rr4.w;
            *(float4*)(C + base) = v;
        } else {
            if (EPI == 1) {
                v.x = fmaxf(v.x, 0.f); v.y = fmaxf(v.y, 0.f);
                v.z = fmaxf(v.z, 0.f); v.w = fmaxf(v.w, 0.f);
            }
            __half h0 = __float2half_rn(v.x), h1 = __float2half_rn(v.y);
            __half h2 = __float2half_rn(v.z), h3 = __float2half_rn(v.w);
            uint2 hp; hp.x = pack_h2(h0, h1); hp.y = pack_h2(h2, h3);
            *(uint2*)(Ch + base) = hp;
            uint2 lp;
            lp.x = pack_h2(__float2half_rn(v.x - __half2float(h0)),
                           __float2half_rn(v.y - __half2float(h1)));
            lp.y = pack_h2(__float2half_rn(v.z - __half2float(h2)),
                           __float2half_rn(v.w - __half2float(h3)));
            *(uint2*)(Cl + base) = lp;
        }
    }
}

// ---------------- fp16 single-pass GEMM (head, 128x128, K32, 3-stage) ----------------
__global__ void __launch_bounds__(256, 2)
gemm16(const __half* __restrict__ Ah, const __half* __restrict__ Bh,
       const float* __restrict__ bias, float* __restrict__ C,
       int N, int K) {
    extern __shared__ char smraw[];
    uint32_t raw = smem_u32(smraw);
    uint32_t sb  = (raw + 255u) & ~255u;
    char* smp    = smraw + (sb - raw);

    const int tid  = threadIdx.x;
    const int lane = tid & 31;
    const int wid  = tid >> 5;
    const int wm   = wid >> 2;
    const int wn   = wid & 3;
    const int m0   = blockIdx.x * 128;
    const int n0   = blockIdx.y * 128;

    const int r_ = tid >> 1;
    const int kh = (tid & 1) * 16;
    const __half* apH = Ah + (size_t)(m0 + r_) * K + kh;
    const int ng = n0 + r_;
    const bool nvB = (ng < N);
    const int ngc = nvB ? ng : (N - 1);
    const uint32_t bsz = nvB ? 16u : 0u;
    const __half* bpH = Bh + (size_t)ngc * K + kh;

    float acc[4][4][4];
    #pragma unroll
    for (int i = 0; i < 4; i++)
        #pragma unroll
        for (int j = 0; j < 4; j++)
            #pragma unroll
            for (int q = 0; q < 4; q++) acc[i][j][q] = 0.f;

    const int NC = K >> 5;
    const uint32_t o0 = aoff(r_, kh), o1 = aoff(r_, kh + 8);

    auto ISSUE = [&](int c) {
        uint32_t b0 = sb + (c % 3) * 16384;
        const int ko = c << 5;
        cp16(b0 + o0,        apH + ko,     16u);
        cp16(b0 + o1,        apH + ko + 8, 16u);
        cp16(b0 + 8192 + o0, bpH + ko,     bsz);
        cp16(b0 + 8192 + o1, bpH + ko + 8, bsz);
    };
    auto MMA = [&](int s) {
        uint32_t base = sb + s * 16384;
        const uint32_t arow = wm * 64 + (lane & 15);
        const uint32_t koffA = (lane & 16) ? 8u : 0u;
        const uint32_t nrow = wn * 32 + (lane & 7) + ((lane & 16) ? 8 : 0);
        const uint32_t koffB = (lane & 8) ? 8u : 0u;
        #pragma unroll
        for (int ks = 0; ks < 2; ks++) {
            uint32_t ah[4][4], bh[4][2];
            #pragma unroll
            for (int mt = 0; mt < 4; mt++) {
                uint32_t off = aoff(arow + mt * 16, ks * 16 + koffA);
                ldmx4(ah[mt], base + off);
            }
            #pragma unroll
            for (int g = 0; g < 2; g++) {
                uint32_t off = aoff(nrow + g * 16, ks * 16 + koffB);
                uint32_t t[4];
                ldmx4(t, base + 8192 + off);
                bh[2*g][0] = t[0]; bh[2*g][1] = t[1];
                bh[2*g+1][0] = t[2]; bh[2*g+1][1] = t[3];
            }
            #pragma unroll
            for (int mt = 0; mt < 4; mt++)
                #pragma unroll
                for (int nt = 0; nt < 4; nt++)
                    mma16816h(acc[mt][nt], ah[mt], bh[nt]);
        }
    };

    ISSUE(0); CP_COMMIT();
    if (NC > 1) { ISSUE(1); CP_COMMIT(); }

    for (int c = 0; c < NC; c++) {
        const int rem = NC - 1 - c;
        if (rem >= 1) CP_WAIT(1);
        else          CP_WAIT(0);
        __syncthreads();
        if (c + 2 < NC) { ISSUE(c + 2); CP_COMMIT(); }
        MMA(c % 3);
    }
    __syncthreads();

    float* stage = (float*)smp;
    {
        const int r0 = wm * 64 + (lane >> 2);
        const int c0 = wn * 32 + (lane & 3) * 2;
        #pragma unroll
        for (int mt = 0; mt < 4; mt++)
            #pragma unroll
            for (int nt = 0; nt < 4; nt++) {
                int r = r0 + mt * 16, cc = c0 + nt * 8;
                float2 p0; p0.x = acc[mt][nt][0]; p0.y = acc[mt][nt][1];
                float2 p1; p1.x = acc[mt][nt][2]; p1.y = acc[mt][nt][3];
                *(float2*)&stage[r * STAGE_LD + cc]       = p0;
                *(float2*)&stage[(r + 8) * STAGE_LD + cc] = p1;
            }
    }
    __syncthreads();

    #pragma unroll 4
    for (int j = 0; j < 16; j++) {
        int lin = j * 256 + tid;
        int rr = lin >> 5;
        int cg = (lin & 31) * 4;
        #pragma unroll
        for (int q = 0; q < 4; q++) {
            int n = n0 + cg + q;
            if (n < N) {
                float v = stage[rr * STAGE_LD + cg + q];
                if (bias) v += bias[n];
                C[(size_t)(m0 + rr) * N + n] = v;
            }
        }
    }
}

// ---------------- LayerNorm core (192 threads, float4) ----------------
__device__ __forceinline__ void ln_body(float4 v, const float* __restrict__ g,
                                        const float* __restrict__ b,
                                        __half* __restrict__ yh, __half* __restrict__ yl,
                                        size_t rb, int tid) {
    float s  = v.x + v.y + v.z + v.w;
    float ss = v.x*v.x + v.y*v.y + v.z*v.z + v.w*v.w;
    #pragma unroll
    for (int off = 16; off > 0; off >>= 1) {
        s  += __shfl_down_sync(0xffffffffu, s,  off);
        ss += __shfl_down_sync(0xffffffffu, ss, off);
    }
    __shared__ float sh_s[6], sh_ss[6];
    int wid = tid >> 5, lane = tid & 31;
    if (lane == 0) { sh_s[wid] = s; sh_ss[wid] = ss; }
    __syncthreads();
    float tot = 0.f, tots = 0.f;
    #pragma unroll
    for (int i = 0; i < 6; i++) { tot += sh_s[i]; tots += sh_ss[i]; }
    float mean = tot * (1.0f / E_);
    float var  = tots * (1.0f / E_) - mean * mean;
    float rstd = rsqrtf(var + EPS);
    float4 gg = *(const float4*)(g + tid * 4);
    float4 bb = *(const float4*)(b + tid * 4);
    float y0 = (v.x - mean) * rstd * gg.x + bb.x;
    float y1 = (v.y - mean) * rstd * gg.y + bb.y;
    float y2 = (v.z - mean) * rstd * gg.z + bb.z;
    float y3 = (v.w - mean) * rstd * gg.w + bb.w;
    __half h0 = __float2half_rn(y0), h1 = __float2half_rn(y1);
    __half h2 = __float2half_rn(y2), h3 = __float2half_rn(y3);
    uint2 hp; hp.x = pack_h2(h0, h1); hp.y = pack_h2(h2, h3);
    *(uint2*)(yh + rb + tid * 4) = hp;
    uint2 lp;
    lp.x = pack_h2(__float2half_rn(y0 - __half2float(h0)),
                   __float2half_rn(y1 - __half2float(h1)));
    lp.y = pack_h2(__float2half_rn(y2 - __half2float(h2)),
                   __float2half_rn(y3 - __half2float(h3)));
    *(uint2*)(yl + rb + tid * 4) = lp;
}

__global__ void ln_kernel(const float* __restrict__ x,
                          const float* __restrict__ g,
                          const float* __restrict__ b,
                          __half* __restrict__ yh, __half* __restrict__ yl) {
    const int row = blockIdx.x, tid = threadIdx.x;
    size_t rb = (size_t)row * E_;
    float4 v = *(const float4*)(x + rb + tid * 4);
    ln_body(v, g, b, yh, yl, rb, tid);
}

__global__ void embed_ln_kernel(const int* __restrict__ idx,
                                const float* __restrict__ tok,
                                const float* __restrict__ pos,
                                const float* __restrict__ g,
                                const float* __restrict__ b,
                                float* __restrict__ x,
                                __half* __restrict__ yh, __half* __restrict__ yl) {
    const int row = blockIdx.x, tid = threadIdx.x;
    const int t = row & (T_ - 1);
    const int token = idx[row];
    float4 tv = *(const float4*)(tok + (size_t)token * E_ + tid * 4);
    float4 pv = *(const float4*)(pos + (size_t)t * E_ + tid * 4);
    float4 v; v.x = tv.x + pv.x; v.y = tv.y + pv.y; v.z = tv.z + pv.z; v.w = tv.w + pv.w;
    size_t rb = (size_t)row * E_;
    *(float4*)(x + rb + tid * 4) = v;
    ln_body(v, g, b, yh, yl, rb, tid);
}

// ---------------- Tensor-core flash attention (fused-QKV input, stride E3) ----------------
__global__ void __launch_bounds__(128, 3)
attn_mma(const __half* __restrict__ QKVh, const __half* __restrict__ QKVl,
         __half* __restrict__ Oh, __half* __restrict__ Ol) {
    extern __shared__ char smraw[];
    uint32_t raw = smem_u32(smraw);
    uint32_t sb  = (raw + 255u) & ~255u;
    char* smp    = smraw + (sb - raw);
    const uint32_t s_kh = sb, s_kl = sb + 8192, s_vh = sb + 16384, s_vl = sb + 24576;
    char *p_kh = smp, *p_kl = smp + 8192, *p_vh = smp + 16384, *p_vl = smp + 24576;

    const int qb = blockIdx.x, bhid = blockIdx.y;
    const int b = bhid / H_, h = bhid % H_;
    const int tid = threadIdx.x, lane = tid & 31, wq = tid >> 5;
    const float scale = rsqrtf((float)E_);

    const uint32_t koffA = (lane & 16) ? 8u : 0u;
    const uint32_t brow  = (lane & 7) + ((lane & 16) ? 8 : 0);
    const uint32_t koffB = (lane & 8) ? 8u : 0u;

    uint32_t aQh[4][4], aQl[4][4];
    {
        int r = tid >> 1, hf = (tid & 1) * 32;
        size_t qoff = (size_t)(b*T_ + qb*64 + r) * E3 + h*64 + hf;
        const uint4* qph = (const uint4*)(QKVh + qoff);
        const uint4* qpl = (const uint4*)(QKVl + qoff);
        #pragma unroll
        for (int j = 0; j < 4; j++) {
            *(uint4*)(p_kh + voff(r, hf + j*8)) = qph[j];
            *(uint4*)(p_kl + voff(r, hf + j*8)) = qpl[j];
        }
        __syncthreads();
        #pragma unroll
        for (int ks = 0; ks < 4; ks++) {
            ldmx4(aQh[ks], s_kh + voff(wq*16 + (lane & 15), ks*16 + koffA));
            ldmx4(aQl[ks], s_kl + voff(wq*16 + (lane & 15), ks*16 + koffA));
        }
        __syncthreads();
    }

    float m0 = -1e30f, m1 = -1e30f, l0 = 0.f, l1 = 0.f;
    float O[8][4];
    #pragma unroll
    for (int nt = 0; nt < 8; nt++)
        #pragma unroll
        for (int q = 0; q < 4; q++) O[nt][q] = 0.f;

    const int q0 = qb*64 + wq*16 + (lane >> 2);
    const int q1 = q0 + 8;

    for (int st0 = 0; st0 <= qb*64; st0 += 64) {
        {
            int s = tid >> 1, hf = (tid & 1) * 32;
            size_t koffg = (size_t)(b*T_ + st0 + s) * E3 + 768 + h*64 + hf;
            size_t voffg = (size_t)(b*T_ + st0 + s) * E3 + 1536 + h*64 + hf;
            const uint4* kph = (const uint4*)(QKVh + koffg);
            const uint4* kpl = (const uint4*)(QKVl + koffg);
            #pragma unroll
            for (int j = 0; j < 4; j++) {
                *(uint4*)(p_kh + voff(s, hf + j*8)) = kph[j];
                *(uint4*)(p_kl + voff(s, hf + j*8)) = kpl[j];
            }
            uint4 tvh[4], tvl[4];
            const uint4* vph = (const uint4*)(QKVh + voffg);
            const uint4* vpl = (const uint4*)(QKVl + voffg);
            #pragma unroll
            for (int j = 0; j < 4; j++) { tvh[j] = vph[j]; tvl[j] = vpl[j]; }
            const __half* hv = (const __half*)tvh;
            const __half* lv = (const __half*)tvl;
            #pragma unroll
            for (int j = 0; j < 32; j++) {
                *(__half*)(p_vh + voff(hf + j, s)) = hv[j];
                *(__half*)(p_vl + voff(hf + j, s)) = lv[j];
            }
        }
        __syncthreads();

        float S[8][4];
        #pragma unroll
        for (int nt = 0; nt < 8; nt++)
            #pragma unroll
            for (int q = 0; q < 4; q++) S[nt][q] = 0.f;
        #pragma unroll
        for (int ks = 0; ks < 4; ks++) {
            uint32_t bKh[8][2], bKl[8][2];
            #pragma unroll
            for (int g = 0; g < 4; g++) {
                uint32_t t[4];
                ldmx4(t, s_kh + voff(g*16 + brow, ks*16 + koffB));
                bKh[2*g][0] = t[0]; bKh[2*g][1] = t[1];
                bKh[2*g+1][0] = t[2]; bKh[2*g+1][1] = t[3];
                ldmx4(t, s_kl + voff(g*16 + brow, ks*16 + koffB));
                bKl[2*g][0] = t[0]; bKl[2*g][1] = t[1];
                bKl[2*g+1][0] = t[2]; bKl[2*g+1][1] = t[3];
            }
            #pragma unroll
            for (int nt = 0; nt < 8; nt++) {
                mma16816h(S[nt], aQh[ks], bKh[nt]);
                mma16816h(S[nt], aQl[ks], bKh[nt]);
                mma16816h(S[nt], aQh[ks], bKl[nt]);
            }
        }

        const bool diag = (st0 == qb*64);
        #pragma unroll
        for (int nt = 0; nt < 8; nt++) {
            S[nt][0] *= scale; S[nt][1] *= scale; S[nt][2] *= scale; S[nt][3] *= scale;
            if (diag) {
                int sg = st0 + nt*8 + (lane & 3)*2;
                if (sg     > q0) S[nt][0] = -1e30f;
                if (sg + 1 > q0) S[nt][1] = -1e30f;
                if (sg     > q1) S[nt][2] = -1e30f;
                if (sg + 1 > q1) S[nt][3] = -1e30f;
            }
        }

        float rx0 = -1e30f, rx1 = -1e30f;
        #pragma unroll
        for (int nt = 0; nt < 8; nt++) {
            rx0 = fmaxf(rx0, fmaxf(S[nt][0], S[nt][1]));
            rx1 = fmaxf(rx1, fmaxf(S[nt][2], S[nt][3]));
        }
        rx0 = fmaxf(rx0, __shfl_xor_sync(0xffffffffu, rx0, 1));
        rx0 = fmaxf(rx0, __shfl_xor_sync(0xffffffffu, rx0, 2));
        rx1 = fmaxf(rx1, __shfl_xor_sync(0xffffffffu, rx1, 1));
        rx1 = fmaxf(rx1, __shfl_xor_sync(0xffffffffu, rx1, 2));
        float mn0 = fmaxf(m0, rx0), mn1 = fmaxf(m1, rx1);
        float c0 = __expf(m0 - mn0), c1 = __expf(m1 - mn1);

        float rs0 = 0.f, rs1 = 0.f;
        uint32_t aPh[4][4], aPl[4][4];
        #pragma unroll
        for (int ks = 0; ks < 4; ks++) {
            #pragma unroll
            for (int hf = 0; hf < 2; hf++) {
                int nt = 2*ks + hf;
                float p0 = __expf(S[nt][0] - mn0);
                float p1 = __expf(S[nt][1] - mn0);
                float p2 = __expf(S[nt][2] - mn1);
                float p3 = __expf(S[nt][3] - mn1);
                rs0 += p0 + p1; rs1 += p2 + p3;
                __half h0 = __float2half_rn(p0), h1 = __float2half_rn(p1);
                __half h2 = __float2half_rn(p2), h3 = __float2half_rn(p3);
                aPh[ks][2*hf]     = pack_h2(h0, h1);
                aPh[ks][2*hf + 1] = pack_h2(h2, h3);
                aPl[ks][2*hf]     = pack_h2(__float2half_rn(p0 - __half2float(h0)),
                                            __float2half_rn(p1 - __half2float(h1)));
                aPl[ks][2*hf + 1] = pack_h2(__float2half_rn(p2 - __half2float(h2)),
                                            __float2half_rn(p3 - __half2float(h3)));
            }
        }
        rs0 += __shfl_xor_sync(0xffffffffu, rs0, 1);
        rs0 += __shfl_xor_sync(0xffffffffu, rs0, 2);
        rs1 += __shfl_xor_sync(0xffffffffu, rs1, 1);
        rs1 += __shfl_xor_sync(0xffffffffu, rs1, 2);
        l0 = l0 * c0 + rs0;
        l1 = l1 * c1 + rs1;

        #pragma unroll
        for (int nt = 0; nt < 8; nt++) {
            O[nt][0] *= c0; O[nt][1] *= c0; O[nt][2] *= c1; O[nt][3] *= c1;
        }

        #pragma unroll
        for (int ks = 0; ks < 4; ks++) {
            uint32_t bVh[8][2], bVl[8][2];
            #pragma unroll
            for (int g = 0; g < 4; g++) {
                uint32_t t[4];
                ldmx4(t, s_vh + voff(g*16 + brow, ks*16 + koffB));
                bVh[2*g][0] = t[0]; bVh[2*g][1] = t[1];
                bVh[2*g+1][0] = t[2]; bVh[2*g+1][1] = t[3];
                ldmx4(t, s_vl + voff(g*16 + brow, ks*16 + koffB));
                bVl[2*g][0] = t[0]; bVl[2*g][1] = t[1];
                bVl[2*g+1][0] = t[2]; bVl[2*g+1][1] = t[3];
            }
            #pragma unroll
            for (int nt = 0; nt < 8; nt++) {
                mma16816h(O[nt], aPh[ks], bVh[nt]);
                mma16816h(O[nt], aPl[ks], bVh[nt]);
                mma16816h(O[nt], aPh[ks], bVl[nt]);
            }
        }
        m0 = mn0; m1 = mn1;
        __syncthreads();
    }

    float i0 = 1.f / l0, i1 = 1.f / l1;
    size_t base0 = (size_t)(b*T_ + q0) * E_ + h*64 + (lane & 3)*2;
    size_t base1 = (size_t)(b*T_ + q1) * E_ + h*64 + (lane & 3)*2;
    #pragma unroll
    for (int nt = 0; nt < 8; nt++) {
        int d = nt * 8;
        float v0 = O[nt][0] * i0, v1 = O[nt][1] * i0;
        float v2 = O[nt][2] * i1, v3 = O[nt][3] * i1;
        __half h0 = __float2half_rn(v0), h1 = __float2half_rn(v1);
        __half h2 = __float2half_rn(v2), h3 = __float2half_rn(v3);
        *(uint32_t*)(Oh + base0 + d) = pack_h2(h0, h1);
        *(uint32_t*)(Oh + base1 + d) = pack_h2(h2, h3);
        *(uint32_t*)(Ol + base0 + d) = pack_h2(__float2half_rn(v0 - __half2float(h0)),
                                               __float2half_rn(v1 - __half2float(h1)));
        *(uint32_t*)(Ol + base1 + d) = pack_h2(__float2half_rn(v2 - __half2float(h2)),
                                               __float2half_rn(v3 - __half2float(h3)));
    }
}

// ---------------- Host launch ----------------
extern "C" void kernel_launch(void* const* d_in, const int* in_sizes, int n_in,
                              void* d_out, int out_size) {
    const int*   idx     = (const int*)  d_in[0];
    const float* tok_emb = (const float*)d_in[1];
    const float* pos_emb = (const float*)d_in[2];
    const float* Wq      = (const float*)d_in[3];
    const float* Wk      = (const float*)d_in[4];
    const float* Wv      = (const float*)d_in[5];
    const float* Wo      = (const float*)d_in[6];
    const float* bo      = (const float*)d_in[7];
    const float* ln1_g   = (const float*)d_in[8];
    const float* ln1_b   = (const float*)d_in[9];
    const float* ln2_g   = (const float*)d_in[10];
    const float* ln2_b   = (const float*)d_in[11];
    const float* W1      = (const float*)d_in[12];
    const float* b1      = (const float*)d_in[13];
    const float* W2      = (const float*)d_in[14];
    const float* b2      = (const float*)d_in[15];
    const float* lnf_g   = (const float*)d_in[16];
    const float* lnf_b   = (const float*)d_in[17];
    const float* Wh      = (const float*)d_in[18];
    const float* bh      = (const float*)d_in[19];
    float* out = (float*)d_out;

    float *x;
    __half *xnh, *xnl, *qkvh, *qkvl, *atth, *attl, *ffh, *ffl, *wh;
    cudaGetSymbolAddress((void**)&x,    g_x);
    cudaGetSymbolAddress((void**)&xnh,  g_xn_h);
    cudaGetSymbolAddress((void**)&xnl,  g_xn_l);
    cudaGetSymbolAddress((void**)&qkvh, g_qkv_h);
    cudaGetSymbolAddress((void**)&qkvl, g_qkv_l);
    cudaGetSymbolAddress((void**)&atth, g_att_h);
    cudaGetSymbolAddress((void**)&attl, g_att_l);
    cudaGetSymbolAddress((void**)&ffh,  g_ff_h);
    cudaGetSymbolAddress((void**)&ffl,  g_ff_l);
    cudaGetSymbolAddress((void**)&wh,   g_w_h);

    cudaFuncSetAttribute((void*)gemm_h2<1>, cudaFuncAttributeMaxDynamicSharedMemorySize, GEMM_SMEM);
    cudaFuncSetAttribute((void*)gemm_h2<2>, cudaFuncAttributeMaxDynamicSharedMemorySize, GEMM_SMEM);
    cudaFuncSetAttribute((void*)gemm_h2<3>, cudaFuncAttributeMaxDynamicSharedMemorySize, GEMM_SMEM);
    cudaFuncSetAttribute((void*)gemm16,     cudaFuncAttributeMaxDynamicSharedMemorySize, GEMM16_SMEM);
    cudaFuncSetAttribute((void*)attn_mma,   cudaFuncAttributeMaxDynamicSharedMemorySize, ATT_SMEM);

    dim3 gQKVsplit(24, 24, 18);
    dim3 gWoAll(24, 24, 6);
    dim3 gW1All(24, 96, 6);
    dim3 gW2All(96, 24, 6);
    dim3 gHd(24, (V_+31)/32);
    dim3 gQKV(64, 18);       // 64x128, N=2304
    dim3 gWo(64, 6);         // 64x128, N=768
    dim3 gFF(64, 24);        // 64x128, N=3072
    dim3 gW2(64, 6);         // 64x128, K=3072
    dim3 gV(32, 393);
    dim3 gAttn(T_ / 64, B_ * H_);

    // QKV GEMM of layer 0 at launch index 3 (ncu window)
    embed_ln_kernel<<<BT, 192>>>(idx, tok_emb, pos_emb, ln1_g, ln1_b, x, xnh, xnl);     // 0
    wsplit_qkv_all<<<gQKVsplit, 256>>>(Wq, Wk, Wv, wh);                                 // 1
    wsplit_all0<<<gWoAll, 256>>>(Wo, (long)E_*E_, wh + WO_OFF, (long)LAYER_SZ, E_, E_); // 2

    for (int l = 0; l < L_; l++) {
        size_t lo = (size_t)l * LAYER_SZ;

        if (l > 0)
            ln_kernel<<<BT, 192>>>(x, ln1_g + (size_t)l * E_, ln1_b + (size_t)l * E_, xnh, xnl);

        gemm_h2<3><<<gQKV, 256, GEMM_SMEM>>>(xnh, xnl, wh + lo,                         // 3 for l=0
                                             nullptr, nullptr, nullptr,
                                             qkvh, qkvl, E3, E_);

        attn_mma<<<gAttn, 128, ATT_SMEM>>>(qkvh, qkvl, atth, attl);

        gemm_h2<2><<<gWo, 256, GEMM_SMEM>>>(atth, attl, wh + lo + WO_OFF,
                                            bo + (size_t)l * E_, x, x,
                                            nullptr, nullptr, E_, E_);

        ln_kernel<<<BT, 192>>>(x, ln2_g + (size_t)l * E_, ln2_b + (size_t)l * E_, xnh, xnl);

        if (l == 0)
            wsplit_all0<<<gW1All, 256>>>(W1, (long)E_*FF, wh + W1_OFF, (long)LAYER_SZ, E_, FF);
        gemm_h2<1><<<gFF, 256, GEMM_SMEM>>>(xnh, xnl, wh + lo + W1_OFF,
                                            b1 + (size_t)l * FF, nullptr, nullptr,
                                            ffh, ffl, FF, E_);

        if (l == 0)
            wsplit_all0<<<gW2All, 256>>>(W2, (long)FF*E_, wh + W2_OFF, (long)LAYER_SZ, FF, E_);
        gemm_h2<2><<<gW2, 256, GEMM_SMEM>>>(ffh, ffl, wh + lo + W2_OFF,
                                            b2 + (size_t)l * E_, x, x,
                                            nullptr, nullptr, E_, FF);
    }

    // fp16 single-pass head
    ln_kernel<<<BT, 192>>>(x, lnf_g, lnf_b, xnh, xnl);
    wsplit16_kernel<<<gHd, 256>>>(Wh, wh + HEAD_OFF, E_, V_);
    gemm16<<<gV, 256, GEMM16_SMEM>>>(xnh, wh + HEAD_OFF, bh, out, V_, E_);

    (void)in_sizes; (void)n_in; (void)out_size;
}